// round 2
// baseline (speedup 1.0000x reference)
#include <cuda_runtime.h>
#include <cuda_fp16.h>

#define EMB   2048
#define NSTEP 2048
#define NB    2
#define G4    (4*EMB)

#define CTAS  128
#define EPC   16          // e-values per CTA
#define NROWS 64          // 4 gates * EPC
#define NTHR  256         // 8 warps
#define NWARP 8
#define RPW   8           // rows per warp (full K per warp)

// K handled as 1024 f32-PAIRS per row:
//   A: pairs [0,192)    -> cols [0,384)     in registers (f32)
//   B: pairs [192,576)  -> cols [384,1152)  in smem (f32, 192KB)
//   C: pairs [576,1024) -> cols [1152,2048) streamed from L2 (fp16)

#define SH_W_F (NROWS*768)          // 49152 floats
#define SH_H_F (NB*EMB)             // 4096 floats
#define SH_G_F (NROWS*2)            // 128 floats
#define SMEM_FLOATS (SH_W_F + SH_H_F + SH_G_F)
#define SMEM_BYTES  (SMEM_FLOATS*4)

__device__ float  g_Wcomb[(size_t)G4*EMB];      // 67 MB f32 (Wih+Whh)
__device__ __half g_Whalf[(size_t)G4*EMB];      // 33.5 MB fp16 copy
__device__ float  g_bcomb[G4];
__device__ float  g_hseq[(size_t)NSTEP*NB*EMB]; // [t][b][e] f32
__device__ int    g_flag[CTAS];

typedef unsigned long long ull;

__device__ __forceinline__ void ffma2(ull &d, ull a, ull b) {
    asm("fma.rn.f32x2 %0, %1, %2, %0;" : "+l"(d) : "l"(a), "l"(b));
}
__device__ __forceinline__ ull dup2(float a) {
    ull r; asm("mov.b64 %0, {%1, %1};" : "=l"(r) : "f"(a)); return r;
}
__device__ __forceinline__ ull pack2(float lo, float hi) {
    ull r; asm("mov.b64 %0, {%1, %2};" : "=l"(r) : "f"(lo), "f"(hi)); return r;
}
__device__ __forceinline__ float2 unpack2(ull v) {
    float2 f; asm("mov.b64 {%0, %1}, %2;" : "=f"(f.x), "=f"(f.y) : "l"(v)); return f;
}
__device__ __forceinline__ ull h2f2(unsigned u) {   // fp16x2 -> f32x2
    __half2 h = *reinterpret_cast<__half2*>(&u);
    float2 f = __half22float2(h);
    return pack2(f.x, f.y);
}
__device__ __forceinline__ float sigmoidf_(float v) {
    return 1.0f / (1.0f + expf(-v));
}

// ---------------------------------------------------------------------------
__global__ void prep_kernel(const float* __restrict__ Wih, const float* __restrict__ Whh,
                            const float* __restrict__ bih, const float* __restrict__ bhh) {
    size_t n = (size_t)G4 * EMB;
    size_t stride = (size_t)gridDim.x * blockDim.x;
    for (size_t i = (size_t)blockIdx.x * blockDim.x + threadIdx.x; i < n; i += stride) {
        float v = Wih[i] + Whh[i];
        g_Wcomb[i] = v;
        g_Whalf[i] = __float2half(v);
    }
    int i = blockIdx.x * blockDim.x + threadIdx.x;
    if (i < G4) g_bcomb[i] = bih[i] + bhh[i];
    if (i < CTAS) g_flag[i] = 0;
}

// ---------------------------------------------------------------------------
// persistent LSTM: 128 CTAs x 256 threads. Warp w owns rows [w*8, w*8+8)
// (row rl: gate=rl>>4, e_local=rl&15) over the FULL K dimension.
// ---------------------------------------------------------------------------
__global__ void __launch_bounds__(NTHR, 1)
lstm_kernel(const float* __restrict__ x, const float* __restrict__ Wih) {
    extern __shared__ float sh[];
    float* sh_w = sh;                    // [64][768]  cols [384,1152)
    float* sh_h = sh + SH_W_F;           // [2][2048]
    float* sh_g = sh_h + SH_H_F;         // [64][2]

    const int tid  = threadIdx.x;
    const int lane = tid & 31;
    const int w    = tid >> 5;
    const int e0   = blockIdx.x * EPC;

    int Rg[RPW];
#pragma unroll
    for (int r = 0; r < RPW; r++) {
        int rl = w * RPW + r;
        Rg[r] = (rl >> 4) * EMB + e0 + (rl & 15);
    }

    // fill smem f32 weights: cols [384,1152) of the CTA's 64 rows
    for (int i = tid; i < NROWS * 192; i += NTHR) {
        int rr = i / 192, c4 = i % 192;
        int grow = (rr >> 4) * EMB + e0 + (rr & 15);
        float4 v = *(const float4*)&g_Wcomb[(size_t)grow * EMB + 384 + c4 * 4];
        *(float4*)&sh_w[rr * 768 + c4 * 4] = v;
    }

    // register f32 weight pairs: p = lane + 32*j, j<6  (cols [0,384))
    ull wreg[RPW][6];
#pragma unroll
    for (int r = 0; r < RPW; r++) {
        const ull* wp = (const ull*)&g_Wcomb[(size_t)Rg[r] * EMB];
#pragma unroll
        for (int j = 0; j < 6; j++) wreg[r][j] = wp[lane + 32 * j];
    }

    float bias[4];
    float c_reg = 0.0f;
    const int my_el = tid >> 1, my_b = tid & 1;
    if (tid < 32) {
#pragma unroll
        for (int g = 0; g < 4; g++) bias[g] = g_bcomb[g * EMB + e0 + my_el];
    }

    for (int t = 0; t < NSTEP; t++) {
        if (t > 0) {
            if (tid < CTAS) {
                while (((volatile int*)g_flag)[tid] < t) { }
            }
            __threadfence();
        }
        __syncthreads();

        // fill sh_h with h_{t-1} (or x for t=0), f32
        {
            const float* src = (t == 0) ? x : &g_hseq[(size_t)(t - 1) * NB * EMB];
            const float4* s4 = (const float4*)src;
            float4* d4 = (float4*)sh_h;
#pragma unroll
            for (int i = 0; i < 4; i++) d4[tid + NTHR * i] = __ldcg(s4 + tid + NTHR * i);
        }
        __syncthreads();

        ull acc[RPW][2];
#pragma unroll
        for (int r = 0; r < RPW; r++) { acc[r][0] = 0ull; acc[r][1] = 0ull; }

        const ull* h0 = (const ull*)&sh_h[0];
        const ull* h1 = (const ull*)&sh_h[EMB];

        if (t == 0) {
            // gates0 = x @ W_ih^T (+bias at owner): stream W_ih once
            for (int j = 0; j < 32; j++) {
                ull ha = h0[lane + 32 * j];
                ull hb = h1[lane + 32 * j];
#pragma unroll
                for (int r = 0; r < RPW; r++) {
                    ull wv = __ldg((const ull*)&Wih[(size_t)Rg[r] * EMB] + lane + 32 * j);
                    ffma2(acc[r][0], wv, ha);
                    ffma2(acc[r][1], wv, hb);
                }
            }
        } else {
            // ---- phase A: register weights ----
#pragma unroll
            for (int j = 0; j < 6; j++) {
                ull ha = h0[lane + 32 * j];
                ull hb = h1[lane + 32 * j];
#pragma unroll
                for (int r = 0; r < RPW; r++) {
                    ffma2(acc[r][0], wreg[r][j], ha);
                    ffma2(acc[r][1], wreg[r][j], hb);
                }
            }
            // ---- phases B (smem f32) + C (L2 fp16), pipelined ----
            uint2 cw[2][RPW];
#pragma unroll
            for (int r = 0; r < RPW; r++)
                cw[0][r] = *(const uint2*)&g_Whalf[(size_t)Rg[r] * EMB + 1152 + 4 * lane];

#pragma unroll
            for (int jj = 0; jj < 7; jj++) {
                const int cur = jj & 1, nxt = cur ^ 1;
                if (jj < 6) {
#pragma unroll
                    for (int r = 0; r < RPW; r++)
                        cw[nxt][r] = *(const uint2*)&g_Whalf[(size_t)Rg[r] * EMB + 1152 + 4 * lane + 128 * (jj + 1)];
                }
                // B jj (jj<6): cols 384 + (4*lane + 128*jj) .. +4
                if (jj < 6) {
                    int hix = 384 + 4 * lane + 128 * jj;
                    float4 hA4 = *(const float4*)&sh_h[hix];
                    float4 hB4 = *(const float4*)&sh_h[EMB + hix];
                    ull hA0 = pack2(hA4.x, hA4.y), hA1 = pack2(hA4.z, hA4.w);
                    ull hB0 = pack2(hB4.x, hB4.y), hB1 = pack2(hB4.z, hB4.w);
#pragma unroll
                    for (int r = 0; r < RPW; r++) {
                        float4 wv = *(const float4*)&sh_w[(w * RPW + r) * 768 + 4 * lane + 128 * jj];
                        ull w0 = pack2(wv.x, wv.y), w1 = pack2(wv.z, wv.w);
                        ffma2(acc[r][0], w0, hA0); ffma2(acc[r][0], w1, hA1);
                        ffma2(acc[r][1], w0, hB0); ffma2(acc[r][1], w1, hB1);
                    }
                }
                // C jj: cols 1152 + (4*lane + 128*jj) .. +4 (fp16 weights)
                {
                    int hix = 1152 + 4 * lane + 128 * jj;
                    float4 hA4 = *(const float4*)&sh_h[hix];
                    float4 hB4 = *(const float4*)&sh_h[EMB + hix];
                    ull hA0 = pack2(hA4.x, hA4.y), hA1 = pack2(hA4.z, hA4.w);
                    ull hB0 = pack2(hB4.x, hB4.y), hB1 = pack2(hB4.z, hB4.w);
#pragma unroll
                    for (int r = 0; r < RPW; r++) {
                        uint2 cv = cw[cur][r];
                        ull w0 = h2f2(cv.x), w1 = h2f2(cv.y);
                        ffma2(acc[r][0], w0, hA0); ffma2(acc[r][0], w1, hA1);
                        ffma2(acc[r][1], w0, hB0); ffma2(acc[r][1], w1, hB1);
                    }
                }
            }
        }

        // warp reduce -> sh_g
#pragma unroll
        for (int r = 0; r < RPW; r++) {
#pragma unroll
            for (int b = 0; b < 2; b++) {
                float2 f = unpack2(acc[r][b]);
                float v = f.x + f.y;
                v += __shfl_xor_sync(0xffffffffu, v, 16);
                v += __shfl_xor_sync(0xffffffffu, v, 8);
                v += __shfl_xor_sync(0xffffffffu, v, 4);
                v += __shfl_xor_sync(0xffffffffu, v, 2);
                v += __shfl_xor_sync(0xffffffffu, v, 1);
                if (lane == 0) sh_g[(w * RPW + r) * 2 + b] = v;
            }
        }
        __syncthreads();

        // owners: activation + state update + publish h
        if (tid < 32) {
            float gi = sh_g[(0 * 16 + my_el) * 2 + my_b] + bias[0];
            float gf = sh_g[(1 * 16 + my_el) * 2 + my_b] + bias[1];
            float gg = sh_g[(2 * 16 + my_el) * 2 + my_b] + bias[2];
            float go = sh_g[(3 * 16 + my_el) * 2 + my_b] + bias[3];
            float cn = sigmoidf_(gf) * c_reg + sigmoidf_(gi) * tanhf(gg);
            c_reg = cn;
            float h = sigmoidf_(go) * tanhf(cn);
            g_hseq[((size_t)t * NB + my_b) * EMB + e0 + my_el] = h;
        }
        __threadfence();
        __syncthreads();
        if (tid == 0) ((volatile int*)g_flag)[blockIdx.x] = t + 1;
    }
}

// ---------------------------------------------------------------------------
// output projection: out[b][t][n] = hseq[t][b][:] . W_out[n][:] + b_out[n]
// M = 4096 (m = t*2+b), N = 2048, K = 2048, FFMA2 micro-kernel
// ---------------------------------------------------------------------------
#define GBM 64
#define GBN 64
#define GBK 16
#define GPAD 4

__global__ void __launch_bounds__(256)
out_gemm_kernel(const float* __restrict__ Wout, const float* __restrict__ bout,
                float* __restrict__ out) {
    __shared__ float As[GBK][GBM + GPAD];
    __shared__ float Bs[GBK][GBN + GPAD];

    const int tid = threadIdx.x;
    const int tx = tid & 15;   // n dir
    const int ty = tid >> 4;   // m dir
    const int m0 = blockIdx.y * GBM;
    const int n0 = blockIdx.x * GBN;

    ull accL[4], accH[4];
#pragma unroll
    for (int i = 0; i < 4; i++) { accL[i] = 0ull; accH[i] = 0ull; }

    const int lm = tid >> 2;
    const int lk = (tid & 3) * 4;

    for (int k0 = 0; k0 < EMB; k0 += GBK) {
        float4 va = *(const float4*)&g_hseq[(size_t)(m0 + lm) * EMB + k0 + lk];
        float4 vb = *(const float4*)&Wout[(size_t)(n0 + lm) * EMB + k0 + lk];
        As[lk + 0][lm] = va.x; As[lk + 1][lm] = va.y;
        As[lk + 2][lm] = va.z; As[lk + 3][lm] = va.w;
        Bs[lk + 0][lm] = vb.x; Bs[lk + 1][lm] = vb.y;
        Bs[lk + 2][lm] = vb.z; Bs[lk + 3][lm] = vb.w;
        __syncthreads();

#pragma unroll
        for (int k = 0; k < GBK; k++) {
            float4 b4 = *(const float4*)&Bs[k][tx * 4];
            ull bL = pack2(b4.x, b4.y);
            ull bH = pack2(b4.z, b4.w);
#pragma unroll
            for (int i = 0; i < 4; i++) {
                ull ai = dup2(As[k][ty * 4 + i]);
                ffma2(accL[i], ai, bL);
                ffma2(accH[i], ai, bH);
            }
        }
        __syncthreads();
    }

#pragma unroll
    for (int i = 0; i < 4; i++) {
        int m = m0 + ty * 4 + i;
        int tt = m >> 1, bb = m & 1;
        float2 l = unpack2(accL[i]);
        float2 h = unpack2(accH[i]);
        float* o = &out[((size_t)bb * NSTEP + tt) * EMB + n0 + tx * 4];
        o[0] = l.x + bout[n0 + tx * 4 + 0];
        o[1] = l.y + bout[n0 + tx * 4 + 1];
        o[2] = h.x + bout[n0 + tx * 4 + 2];
        o[3] = h.y + bout[n0 + tx * 4 + 3];
    }
}

// ---------------------------------------------------------------------------
extern "C" void kernel_launch(void* const* d_in, const int* in_sizes, int n_in,
                              void* d_out, int out_size) {
    const float* x    = (const float*)d_in[0];
    const float* Wih  = (const float*)d_in[1];
    const float* Whh  = (const float*)d_in[2];
    const float* bih  = (const float*)d_in[3];
    const float* bhh  = (const float*)d_in[4];
    const float* Wout = (const float*)d_in[5];
    const float* bout = (const float*)d_in[6];
    float* out = (float*)d_out;

    cudaFuncSetAttribute(lstm_kernel, cudaFuncAttributeMaxDynamicSharedMemorySize, SMEM_BYTES);

    prep_kernel<<<4096, 256>>>(Wih, Whh, bih, bhh);
    lstm_kernel<<<CTAS, NTHR, SMEM_BYTES>>>(x, Wih);
    dim3 ggrid(EMB / GBN, (NSTEP * NB) / GBM);
    out_gemm_kernel<<<ggrid, 256>>>(Wout, bout, out);
}